// round 13
// baseline (speedup 1.0000x reference)
#include <cuda_runtime.h>
#include <math.h>

#define HH 192
#define WW 192
#define HW (192*192)

typedef unsigned long long u64;

// ---- packed fp32x2 helpers ----
__device__ __forceinline__ u64 pack2(float a, float b) {
    u64 r; asm("mov.b64 %0, {%1, %2};" : "=l"(r) : "f"(a), "f"(b)); return r;
}
__device__ __forceinline__ float2 unpack2(u64 v) {
    float2 f; asm("mov.b64 {%0, %1}, %2;" : "=f"(f.x), "=f"(f.y) : "l"(v)); return f;
}
__device__ __forceinline__ u64 fma2(u64 a, u64 b, u64 c) {
    u64 d; asm("fma.rn.f32x2 %0, %1, %2, %3;" : "=l"(d) : "l"(a), "l"(b), "l"(c)); return d;
}
__device__ __forceinline__ u64 mul2(u64 a, u64 b) {
    u64 d; asm("mul.rn.f32x2 %0, %1, %2;" : "=l"(d) : "l"(a), "l"(b)); return d;
}
// ---- fast transcendentals ----
__device__ __forceinline__ float tanh_fast(float x) {
    float y; asm("tanh.approx.f32 %0, %1;" : "=f"(y) : "f"(x)); return y;
}
__device__ __forceinline__ float sigmoid_fast(float x) {
    float e; asm("ex2.approx.f32 %0, %1;" : "=f"(e) : "f"(-x * 1.4426950408889634f));
    return __frcp_rn(1.f + e);
}

// ---- cp.async helpers ----
__device__ __forceinline__ void cp4(unsigned daddr, const float* src, bool valid) {
    asm volatile("cp.async.ca.shared.global [%0], [%1], 4, %2;"
                 :: "r"(daddr), "l"(src), "r"(valid ? 4u : 0u));
}
__device__ __forceinline__ void cp8(unsigned daddr, const void* src) {
    asm volatile("cp.async.ca.shared.global [%0], [%1], 8;" :: "r"(daddr), "l"(src));
}
__device__ __forceinline__ void cp16(unsigned daddr, const void* src) {
    asm volatile("cp.async.cg.shared.global [%0], [%1], 16;" :: "r"(daddr), "l"(src));
}
__device__ __forceinline__ void cp_commit() {
    asm volatile("cp.async.commit_group;");
}
template<int N> __device__ __forceinline__ void cp_wait() {
    asm volatile("cp.async.wait_group %0;" :: "n"(N));
}

// ---- scratch ----
__device__ float g_h1[64 * HW];
__device__ float g_h2[64 * HW];
__device__ float g_out4[432 * HW];
__device__ float g_xT[HW * 128];
__device__ __align__(16) u64 g_pw1[8  * 192 * 36];
__device__ __align__(16) u64 g_pw2[8  *  64 * 36];
__device__ __align__(16) u64 g_pw3[8  *  64 * 36];
__device__ __align__(16) u64 g_pw4[54 *  64 * 36];
__device__ __align__(16) u64 g_pwdT[16 * 72 * 64];  // deform w: [g][j][oc], dup pairs

// ============================================================================
// Merged prepack kernel (5 segments).
// ============================================================================
__device__ __forceinline__ void conv_pack(const float* wt, int CIN,
                                          u64* dst, int idx)
{
    int kk = idx % 9; int t = idx / 9;
    int pr = t % 4; t /= 4;
    int ci = t % CIN; int ocg = t / CIN;
    float wa = wt[((ocg * 8 + pr)     * CIN + ci) * 9 + kk];
    float wb = wt[((ocg * 8 + pr + 4) * CIN + ci) * 9 + kk];
    dst[idx] = pack2(wa, wb);
}

__global__ void prepack_all_kernel(
    const float* __restrict__ w1, const float* __restrict__ w2,
    const float* __restrict__ w3, const float* __restrict__ w4,
    const float* __restrict__ wd,
    u64* __restrict__ pw1, u64* __restrict__ pw2,
    u64* __restrict__ pw3, u64* __restrict__ pw4,
    u64* __restrict__ pwdT)
{
    int i = blockIdx.x * 256 + threadIdx.x;
    if (i < 55296)            conv_pack(w1, 192, pw1, i);
    else if (i < 73728)       conv_pack(w2,  64, pw2, i - 55296);
    else if (i < 92160)       conv_pack(w3,  64, pw3, i - 73728);
    else if (i < 216576)      conv_pack(w4,  64, pw4, i - 92160);
    else if (i < 290304) {
        int idx = i - 216576;            // [g][j][o]
        int o = idx & 63;
        int j = (idx >> 6) % 72;
        int g = idx / (72 * 64);
        float w = wd[o * 1152 + g * 72 + j];
        pwdT[idx] = pack2(w, w);
    }
}

// ============================================================================
// Direct 3x3 conv, FFMA2 + cp.async pipeline.
// NEW: 8x64 px tile, 128-thread CTAs, 48.5KB smem -> 4 CTAs/SM (finer
// barriers, CTA-level compute/prefetch overlap).
// ============================================================================
#define SIN_ELEMS (8*10*68)
#define SMEM_W_OFF (2*SIN_ELEMS*4)
#define WCHUNK 384                       // 8*3*4*4 u64 per buffer

template<int CIN, bool RELU>
__global__ void __launch_bounds__(128, 4) conv3x3_kernel(
    const float* __restrict__ in,
    const u64*   __restrict__ pw,
    const float* __restrict__ bs,
    float* __restrict__ out)
{
    extern __shared__ char dsm[];
    float* s_in = (float*)dsm;                 // [2][8][10][68]
    u64*   s_w  = (u64*)(dsm + SMEM_W_OFF);    // [2][WCHUNK]

    const int tid  = threadIdx.x;
    const int tx   = tid & 15;                 // 4 px each along w
    const int ty   = tid >> 4;                 // row 0..7
    const int lane = tid & 31;
    const int wid  = tid >> 5;                 // 0..3
    const int bw   = blockIdx.x * 64;
    const int bh   = blockIdx.y * 8;
    const int bz   = blockIdx.z;
    const int ocg0 = bz * 8;
    const int NC   = CIN / 8;

    unsigned sin_addr = (unsigned)__cvta_generic_to_shared(s_in);
    unsigned sw_addr  = (unsigned)__cvta_generic_to_shared(s_w);

    auto prefetch = [&](int chunk, int buf) {
        int ci0 = chunk * 8;
        unsigned dbase = sin_addr + buf * (SIN_ELEMS * 4);
        const float* ibase = in + (size_t)ci0 * HW;
        for (int row = wid; row < 80; row += 4) {
            int cc = row / 10;
            int r  = row - cc * 10;
            int gy = bh - 1 + r;
            bool yok = (unsigned)gy < (unsigned)HH;
            int gyc = min(max(gy, 0), HH - 1);
            const float* src = ibase + (size_t)cc * HW + gyc * WW;
            unsigned drow = dbase + ((cc * 10 + r) * 68) * 4;
            #pragma unroll
            for (int s = 0; s < 3; s++) {
                int c0 = lane + s * 32;
                if (c0 < 66) {
                    int gx = bw - 1 + c0;
                    bool ok = yok && (unsigned)gx < (unsigned)WW;
                    int gxc = min(max(gx, 0), WW - 1);
                    cp4(drow + c0 * 4, src + gxc, ok);
                }
            }
        }
        // weights -> padded [cc][kh][pr][4] layout, 8B copies
        const u64* wsrc = pw + (size_t)(bz * CIN + ci0) * 36;
        unsigned wdst = sw_addr + buf * (WCHUNK * 8);
        for (int li = tid; li < 288; li += 128) {
            int cc = li / 36, r  = li - cc * 36;
            int kh = r / 12,  r2 = r - kh * 12;
            int pr = r2 / 3,  kw = r2 - pr * 3;
            cp8(wdst + (((cc * 3 + kh) * 4 + pr) * 4 + kw) * 8,
                wsrc + (cc * 4 + pr) * 9 + kh * 3 + kw);
        }
    };

    u64 acc[4][4];
    #pragma unroll
    for (int p = 0; p < 4; p++)
        #pragma unroll
        for (int q = 0; q < 4; q++) acc[p][q] = 0ull;

    prefetch(0, 0);
    cp_commit();

    for (int c = 0; c < NC; c++) {
        if (c + 1 < NC) {
            prefetch(c + 1, (c + 1) & 1);
            cp_commit();
            cp_wait<1>();
        } else {
            cp_wait<0>();
        }
        __syncthreads();

        const int buf = c & 1;
        const float* sin = s_in + buf * SIN_ELEMS;
        const u64*   sw  = s_w  + buf * WCHUNK;

        #pragma unroll
        for (int cc = 0; cc < 8; cc++) {
            #pragma unroll
            for (int kh = 0; kh < 3; kh++) {
                const float* rp = sin + ((cc * 10) + ty + kh) * 68 + tx * 4;
                float4 a = *(const float4*)rp;
                float2 b = *(const float2*)(rp + 4);
                u64 d[6];
                d[0] = pack2(a.x, a.x);
                d[1] = pack2(a.y, a.y);
                d[2] = pack2(a.z, a.z);
                d[3] = pack2(a.w, a.w);
                d[4] = pack2(b.x, b.x);
                d[5] = pack2(b.y, b.y);
                #pragma unroll
                for (int pr = 0; pr < 4; pr++) {
                    const u64* wr = sw + ((cc * 3 + kh) * 4 + pr) * 4;
                    ulonglong2 w01 = *(const ulonglong2*)wr;   // LDS.128
                    u64 w2 = wr[2];                            // LDS.64
                    #pragma unroll
                    for (int px = 0; px < 4; px++) {
                        acc[pr][px] = fma2(w01.x, d[px],     acc[pr][px]);
                        acc[pr][px] = fma2(w01.y, d[px + 1], acc[pr][px]);
                        acc[pr][px] = fma2(w2,    d[px + 2], acc[pr][px]);
                    }
                }
            }
        }
        __syncthreads();
    }

    const size_t obase = (size_t)(bh + ty) * WW + bw + tx * 4;
    #pragma unroll
    for (int pr = 0; pr < 4; pr++) {
        float bva = bs[ocg0 + pr];
        float bvb = bs[ocg0 + pr + 4];
        float ra[4], rb[4];
        #pragma unroll
        for (int px = 0; px < 4; px++) {
            float2 f = unpack2(acc[pr][px]);
            float va = f.x + bva;
            float vb = f.y + bvb;
            if (RELU) {
                va = (va >= 0.f) ? va : 0.1f * va;
                vb = (vb >= 0.f) ? vb : 0.1f * vb;
            }
            ra[px] = va; rb[px] = vb;
        }
        *(float4*)&out[(size_t)(ocg0 + pr)     * HW + obase] =
            make_float4(ra[0], ra[1], ra[2], ra[3]);
        *(float4*)&out[(size_t)(ocg0 + pr + 4) * HW + obase] =
            make_float4(rb[0], rb[1], rb[2], rb[3]);
    }
}

#define CONV_SMEM (2*SIN_ELEMS*4 + 2*WCHUNK*8)

// ============================================================================
// Transpose x: [128][HW] -> [HW][128].
// ============================================================================
__global__ void __launch_bounds__(256) transpose_kernel(
    const float* __restrict__ x, float* __restrict__ xT)
{
    __shared__ float s[32][33];
    int p0 = blockIdx.x * 32;
    int c0 = blockIdx.y * 32;
    int tx = threadIdx.x & 31;
    int ty = threadIdx.x >> 5;
    #pragma unroll
    for (int i = 0; i < 32; i += 8)
        s[ty + i][tx] = x[(size_t)(c0 + ty + i) * HW + p0 + tx];
    __syncthreads();
    #pragma unroll
    for (int i = 0; i < 32; i += 8)
        xT[(size_t)(p0 + ty + i) * 128 + c0 + tx] = s[tx][ty + i];
}

// ============================================================================
// Fused deformable conv v4 (unchanged): 64 px/block, transposed weights,
// double-buffered weights + val.
// ============================================================================
#define DPX 64
#define VAL_ELEMS (72 * DPX)
#define WG_ELEMS (72 * 64)
#define DEF_SMEM (2*VAL_ELEMS*4 + 2*WG_ELEMS*8)

__global__ void __launch_bounds__(256, 2) deform_kernel(
    const float* __restrict__ xT,
    const float* __restrict__ out4,
    const u64*   __restrict__ pwdT,
    const float* __restrict__ bs,
    float* __restrict__ out)
{
    extern __shared__ char dsm2[];
    float* val_s = (float*)dsm2;
    u64*   w_s   = (u64*)(dsm2 + 2 * VAL_ELEMS * 4);

    const int tid = threadIdx.x;
    const int pbase = blockIdx.x * DPX;
    const int o  = tid & 31;
    const int ps = tid >> 5;

    unsigned w_addr = (unsigned)__cvta_generic_to_shared(w_s);

    auto prefetch_w = [&](int g, int buf) {
        unsigned dbase = w_addr + buf * (WG_ELEMS * 8);
        const u64* src = pwdT + (size_t)g * WG_ELEMS;
        for (int li = tid; li < 2304; li += 256)
            cp16(dbase + li * 16, src + li * 2);
    };

    auto build_val = [&](int g, int buf) {
        float* vb = val_s + buf * VAL_ELEMS;
        for (int t = tid; t < 9 * DPX; t += 256) {
            int pix = t & (DPX - 1);
            int k   = t >> 6;
            int p   = pbase + pix;
            int ho  = p / WW;
            int wo  = p - ho * WW;

            float offy = 5.f * tanh_fast(out4[(g * 18 + k * 2)     * HW + p]);
            float offx = 5.f * tanh_fast(out4[(g * 18 + k * 2 + 1) * HW + p]);
            float mv   = sigmoid_fast(out4[(288 + g * 9 + k) * HW + p]);

            float py = (float)(ho - 1 + k / 3) + offy;
            float px = (float)(wo - 1 + k % 3) + offx;
            float y0 = floorf(py), x0 = floorf(px);
            float wy1 = py - y0, wx1 = px - x0;

            u64 v2[4] = {0ull, 0ull, 0ull, 0ull};

            auto corner = [&](float yf, float xf, float wc) {
                if (yf >= 0.f && yf <= (float)(HH - 1) &&
                    xf >= 0.f && xf <= (float)(WW - 1)) {
                    int iy = (int)yf, ix = (int)xf;
                    const ulonglong2* q =
                        (const ulonglong2*)(xT + ((size_t)(iy * WW + ix) << 7) + (g << 3));
                    ulonglong2 q0 = q[0], q1 = q[1];
                    u64 wc2 = pack2(wc, wc);
                    v2[0] = fma2(wc2, q0.x, v2[0]);
                    v2[1] = fma2(wc2, q0.y, v2[1]);
                    v2[2] = fma2(wc2, q1.x, v2[2]);
                    v2[3] = fma2(wc2, q1.y, v2[3]);
                }
            };
            corner(y0,       x0,       (1.f - wy1) * (1.f - wx1));
            corner(y0,       x0 + 1.f, (1.f - wy1) * wx1);
            corner(y0 + 1.f, x0,       wy1 * (1.f - wx1));
            corner(y0 + 1.f, x0 + 1.f, wy1 * wx1);

            u64 m2 = pack2(mv, mv);
            #pragma unroll
            for (int c2 = 0; c2 < 4; c2++) {
                float2 ff = unpack2(mul2(v2[c2], m2));
                vb[((c2 * 2)     * 9 + k) * DPX + pix] = ff.x;
                vb[((c2 * 2 + 1) * 9 + k) * DPX + pix] = ff.y;
            }
        }
    };

    u64 acc[2][4];
    #pragma unroll
    for (int a = 0; a < 2; a++)
        #pragma unroll
        for (int b = 0; b < 4; b++) acc[a][b] = 0ull;

    prefetch_w(0, 0);
    cp_commit();
    build_val(0, 0);

    for (int g = 0; g < 16; g++) {
        const int buf = g & 1;
        cp_wait<0>();
        __syncthreads();

        if (g < 15) {
            prefetch_w(g + 1, buf ^ 1);
            cp_commit();
        }

        const u64*   wb = w_s + buf * WG_ELEMS;
        const float* vv = val_s + buf * VAL_ELEMS + ps * 8;
        #pragma unroll 4
        for (int j = 0; j < 72; j++) {
            u64 w0 = wb[j * 64 + o];
            u64 w1 = wb[j * 64 + o + 32];
            const u64* vp = (const u64*)(vv + j * DPX);
            u64 v0 = vp[0], v1 = vp[1], v2 = vp[2], v3 = vp[3];
            acc[0][0] = fma2(w0, v0, acc[0][0]);
            acc[0][1] = fma2(w0, v1, acc[0][1]);
            acc[0][2] = fma2(w0, v2, acc[0][2]);
            acc[0][3] = fma2(w0, v3, acc[0][3]);
            acc[1][0] = fma2(w1, v0, acc[1][0]);
            acc[1][1] = fma2(w1, v1, acc[1][1]);
            acc[1][2] = fma2(w1, v2, acc[1][2]);
            acc[1][3] = fma2(w1, v3, acc[1][3]);
        }

        if (g < 15) build_val(g + 1, buf ^ 1);
    }

    float bv0 = bs[o], bv1 = bs[o + 32];
    float r0[8], r1[8];
    #pragma unroll
    for (int b = 0; b < 4; b++) {
        float2 fa = unpack2(acc[0][b]);
        float2 fb = unpack2(acc[1][b]);
        r0[b * 2] = fa.x + bv0; r0[b * 2 + 1] = fa.y + bv0;
        r1[b * 2] = fb.x + bv1; r1[b * 2 + 1] = fb.y + bv1;
    }
    float* o0 = &out[(size_t)o        * HW + pbase + ps * 8];
    float* o1 = &out[(size_t)(o + 32) * HW + pbase + ps * 8];
    *(float4*)(o0)     = make_float4(r0[0], r0[1], r0[2], r0[3]);
    *(float4*)(o0 + 4) = make_float4(r0[4], r0[5], r0[6], r0[7]);
    *(float4*)(o1)     = make_float4(r1[0], r1[1], r1[2], r1[3]);
    *(float4*)(o1 + 4) = make_float4(r1[4], r1[5], r1[6], r1[7]);
}

// ============================================================================
// launch
// ============================================================================
extern "C" void kernel_launch(void* const* d_in, const int* in_sizes, int n_in,
                              void* d_out, int out_size)
{
    const float* x      = (const float*)d_in[0];
    const float* cond   = (const float*)d_in[1];
    const float* weight = (const float*)d_in[2];
    const float* bias   = (const float*)d_in[3];
    const float* w1     = (const float*)d_in[4];
    const float* b1     = (const float*)d_in[5];
    const float* w2     = (const float*)d_in[6];
    const float* b2     = (const float*)d_in[7];
    const float* w3     = (const float*)d_in[8];
    const float* b3     = (const float*)d_in[9];
    const float* w4     = (const float*)d_in[10];
    const float* b4     = (const float*)d_in[11];
    float* out = (float*)d_out;

    float *h1, *h2, *o4, *xT;
    u64 *pw1, *pw2, *pw3, *pw4, *pwdT;
    cudaGetSymbolAddress((void**)&h1, g_h1);
    cudaGetSymbolAddress((void**)&h2, g_h2);
    cudaGetSymbolAddress((void**)&o4, g_out4);
    cudaGetSymbolAddress((void**)&xT, g_xT);
    cudaGetSymbolAddress((void**)&pw1, g_pw1);
    cudaGetSymbolAddress((void**)&pw2, g_pw2);
    cudaGetSymbolAddress((void**)&pw3, g_pw3);
    cudaGetSymbolAddress((void**)&pw4, g_pw4);
    cudaGetSymbolAddress((void**)&pwdT, g_pwdT);

    prepack_all_kernel<<<(290304 + 255) / 256, 256>>>(
        w1, w2, w3, w4, weight, pw1, pw2, pw3, pw4, pwdT);

    cudaFuncSetAttribute(conv3x3_kernel<192, true>,
                         cudaFuncAttributeMaxDynamicSharedMemorySize, CONV_SMEM);
    cudaFuncSetAttribute(conv3x3_kernel<64, true>,
                         cudaFuncAttributeMaxDynamicSharedMemorySize, CONV_SMEM);
    cudaFuncSetAttribute(conv3x3_kernel<64, false>,
                         cudaFuncAttributeMaxDynamicSharedMemorySize, CONV_SMEM);
    cudaFuncSetAttribute(deform_kernel,
                         cudaFuncAttributeMaxDynamicSharedMemorySize, DEF_SMEM);

    dim3 cgrid(3, 24, 8);
    conv3x3_kernel<192, true ><<<cgrid, 128, CONV_SMEM>>>(cond, pw1, b1, h1);
    conv3x3_kernel< 64, true ><<<cgrid, 128, CONV_SMEM>>>(h1,   pw2, b2, h2);
    conv3x3_kernel< 64, true ><<<cgrid, 128, CONV_SMEM>>>(h2,   pw3, b3, h1);
    dim3 cgrid4(3, 24, 54);
    conv3x3_kernel< 64, false><<<cgrid4, 128, CONV_SMEM>>>(h1,  pw4, b4, o4);

    transpose_kernel<<<dim3(1152, 4), 256>>>(x, xT);

    deform_kernel<<<HW / DPX, 256, DEF_SMEM>>>(xT, o4, pwdT, bias, out);
}

// round 15
// speedup vs baseline: 1.1135x; 1.1135x over previous
#include <cuda_runtime.h>
#include <math.h>

#define HH 192
#define WW 192
#define HW (192*192)

typedef unsigned long long u64;

// ---- packed fp32x2 helpers ----
__device__ __forceinline__ u64 pack2(float a, float b) {
    u64 r; asm("mov.b64 %0, {%1, %2};" : "=l"(r) : "f"(a), "f"(b)); return r;
}
__device__ __forceinline__ float2 unpack2(u64 v) {
    float2 f; asm("mov.b64 {%0, %1}, %2;" : "=f"(f.x), "=f"(f.y) : "l"(v)); return f;
}
__device__ __forceinline__ u64 fma2(u64 a, u64 b, u64 c) {
    u64 d; asm("fma.rn.f32x2 %0, %1, %2, %3;" : "=l"(d) : "l"(a), "l"(b), "l"(c)); return d;
}
__device__ __forceinline__ u64 mul2(u64 a, u64 b) {
    u64 d; asm("mul.rn.f32x2 %0, %1, %2;" : "=l"(d) : "l"(a), "l"(b)); return d;
}
// ---- fast transcendentals ----
__device__ __forceinline__ float tanh_fast(float x) {
    float y; asm("tanh.approx.f32 %0, %1;" : "=f"(y) : "f"(x)); return y;
}
__device__ __forceinline__ float sigmoid_fast(float x) {
    float e; asm("ex2.approx.f32 %0, %1;" : "=f"(e) : "f"(-x * 1.4426950408889634f));
    return __frcp_rn(1.f + e);
}

// ---- cp.async helpers ----
__device__ __forceinline__ void cp4(unsigned daddr, const float* src, bool valid) {
    asm volatile("cp.async.ca.shared.global [%0], [%1], 4, %2;"
                 :: "r"(daddr), "l"(src), "r"(valid ? 4u : 0u));
}
__device__ __forceinline__ void cp8(unsigned daddr, const void* src) {
    asm volatile("cp.async.ca.shared.global [%0], [%1], 8;" :: "r"(daddr), "l"(src));
}
__device__ __forceinline__ void cp16(unsigned daddr, const void* src) {
    asm volatile("cp.async.cg.shared.global [%0], [%1], 16;" :: "r"(daddr), "l"(src));
}
__device__ __forceinline__ void cp16z(unsigned daddr, const void* src, bool valid) {
    asm volatile("cp.async.cg.shared.global [%0], [%1], 16, %2;"
                 :: "r"(daddr), "l"(src), "r"(valid ? 16u : 0u));
}
__device__ __forceinline__ void cp_commit() {
    asm volatile("cp.async.commit_group;");
}
template<int N> __device__ __forceinline__ void cp_wait() {
    asm volatile("cp.async.wait_group %0;" :: "n"(N));
}

// ---- tf32 mma helpers ----
__device__ __forceinline__ unsigned cvt_tf32(float x) {
    unsigned u; asm("cvt.rna.tf32.f32 %0, %1;" : "=r"(u) : "f"(x)); return u;
}
__device__ __forceinline__ void mma_tf32(float* c, const unsigned* a, const unsigned* b) {
    asm volatile("mma.sync.aligned.m16n8k8.row.col.f32.tf32.tf32.f32 "
        "{%0,%1,%2,%3}, {%4,%5,%6,%7}, {%8,%9}, {%0,%1,%2,%3};"
        : "+f"(c[0]), "+f"(c[1]), "+f"(c[2]), "+f"(c[3])
        : "r"(a[0]), "r"(a[1]), "r"(a[2]), "r"(a[3]), "r"(b[0]), "r"(b[1]));
}

// ---- scratch ----
__device__ float g_h1[64 * HW];
__device__ float g_h2[64 * HW];
__device__ float g_h1T[HW * 64];
__device__ float g_out4[432 * HW];
__device__ float g_xT[HW * 128];
__device__ __align__(16) u64 g_pw1[8 * 192 * 36];
__device__ __align__(16) u64 g_pw2[8 *  64 * 36];
__device__ __align__(16) u64 g_pw3[8 *  64 * 36];
__device__ __align__(16) u64 g_pwdT[16 * 72 * 64];
__device__ __align__(16) float g_w4Thi[9 * 64 * 432];   // [tap][ci][oc], tf32-hi
__device__ __align__(16) float g_w4Tlo[9 * 64 * 432];   // residual tf32-lo

// ============================================================================
// Merged prepack kernel.
// ============================================================================
__device__ __forceinline__ void conv_pack(const float* wt, int CIN,
                                          u64* dst, int idx)
{
    int kk = idx % 9; int t = idx / 9;
    int pr = t % 4; t /= 4;
    int ci = t % CIN; int ocg = t / CIN;
    float wa = wt[((ocg * 8 + pr)     * CIN + ci) * 9 + kk];
    float wb = wt[((ocg * 8 + pr + 4) * CIN + ci) * 9 + kk];
    dst[idx] = pack2(wa, wb);
}

__global__ void prepack_all_kernel(
    const float* __restrict__ w1, const float* __restrict__ w2,
    const float* __restrict__ w3, const float* __restrict__ w4,
    const float* __restrict__ wd,
    u64* __restrict__ pw1, u64* __restrict__ pw2, u64* __restrict__ pw3,
    u64* __restrict__ pwdT, float* __restrict__ w4Thi, float* __restrict__ w4Tlo)
{
    int i = blockIdx.x * 256 + threadIdx.x;
    if (i < 55296)            conv_pack(w1, 192, pw1, i);
    else if (i < 73728)       conv_pack(w2,  64, pw2, i - 55296);
    else if (i < 92160)       conv_pack(w3,  64, pw3, i - 73728);
    else if (i < 165888) {
        int idx = i - 92160;             // [g][j][o]
        int o = idx & 63;
        int j = (idx >> 6) % 72;
        int g = idx / (72 * 64);
        float w = wd[o * 1152 + g * 72 + j];
        pwdT[idx] = pack2(w, w);
    } else if (i < 414720) {
        int idx = i - 165888;            // [tap][ci][oc]
        int oc  = idx % 432;
        int ci  = (idx / 432) % 64;
        int tap = idx / (432 * 64);
        float w = w4[oc * 576 + ci * 9 + tap];
        unsigned hi = cvt_tf32(w);
        float hif = __uint_as_float(hi);
        unsigned lo = cvt_tf32(w - hif);
        w4Thi[idx] = hif;
        w4Tlo[idx] = __uint_as_float(lo);
    }
}

// ============================================================================
// Direct 3x3 conv (FFMA2 pipelined, 256-thr) — convs 1-3.
// ============================================================================
#define SIN_ELEMS (8*18*68)
#define SMEM_W_OFF (2*SIN_ELEMS*4)
#define WCHUNK 384

template<int CIN, bool RELU>
__global__ void __launch_bounds__(256, 2) conv3x3_kernel(
    const float* __restrict__ in,
    const u64*   __restrict__ pw,
    const float* __restrict__ bs,
    float* __restrict__ out)
{
    extern __shared__ char dsm[];
    float* s_in = (float*)dsm;
    u64*   s_w  = (u64*)(dsm + SMEM_W_OFF);

    const int tid  = threadIdx.x;
    const int tx   = tid & 15;
    const int ty   = tid >> 4;
    const int lane = tid & 31;
    const int wid  = tid >> 5;
    const int bw   = blockIdx.x * 64;
    const int bh   = blockIdx.y * 16;
    const int bz   = blockIdx.z;
    const int ocg0 = bz * 8;
    const int NC   = CIN / 8;

    unsigned sin_addr = (unsigned)__cvta_generic_to_shared(s_in);
    unsigned sw_addr  = (unsigned)__cvta_generic_to_shared(s_w);

    auto prefetch = [&](int chunk, int buf) {
        int ci0 = chunk * 8;
        unsigned dbase = sin_addr + buf * (SIN_ELEMS * 4);
        const float* ibase = in + (size_t)ci0 * HW;
        for (int row = wid; row < 144; row += 8) {
            int cc = row / 18;
            int r  = row - cc * 18;
            int gy = bh - 1 + r;
            bool yok = (unsigned)gy < (unsigned)HH;
            int gyc = min(max(gy, 0), HH - 1);
            const float* src = ibase + (size_t)cc * HW + gyc * WW;
            unsigned drow = dbase + ((cc * 18 + r) * 68) * 4;
            #pragma unroll
            for (int s = 0; s < 3; s++) {
                int c0 = lane + s * 32;
                if (c0 < 66) {
                    int gx = bw - 1 + c0;
                    bool ok = yok && (unsigned)gx < (unsigned)WW;
                    int gxc = min(max(gx, 0), WW - 1);
                    cp4(drow + c0 * 4, src + gxc, ok);
                }
            }
        }
        const u64* wsrc = pw + (size_t)(bz * CIN + ci0) * 36;
        unsigned wdst = sw_addr + buf * (WCHUNK * 8);
        for (int li = tid; li < 288; li += 256) {
            int cc = li / 36, r  = li - cc * 36;
            int kh = r / 12,  r2 = r - kh * 12;
            int pr = r2 / 3,  kw = r2 - pr * 3;
            cp8(wdst + (((cc * 3 + kh) * 4 + pr) * 4 + kw) * 8,
                wsrc + (cc * 4 + pr) * 9 + kh * 3 + kw);
        }
    };

    u64 acc[4][4];
    #pragma unroll
    for (int p = 0; p < 4; p++)
        #pragma unroll
        for (int q = 0; q < 4; q++) acc[p][q] = 0ull;

    prefetch(0, 0);
    cp_commit();

    for (int c = 0; c < NC; c++) {
        if (c + 1 < NC) {
            prefetch(c + 1, (c + 1) & 1);
            cp_commit();
            cp_wait<1>();
        } else {
            cp_wait<0>();
        }
        __syncthreads();

        const int buf = c & 1;
        const float* sin = s_in + buf * SIN_ELEMS;
        const u64*   sw  = s_w  + buf * WCHUNK;

        #pragma unroll
        for (int cc = 0; cc < 8; cc++) {
            #pragma unroll
            for (int kh = 0; kh < 3; kh++) {
                const float* rp = sin + ((cc * 18) + ty + kh) * 68 + tx * 4;
                float4 a = *(const float4*)rp;
                float2 b = *(const float2*)(rp + 4);
                u64 d[6];
                d[0] = pack2(a.x, a.x);
                d[1] = pack2(a.y, a.y);
                d[2] = pack2(a.z, a.z);
                d[3] = pack2(a.w, a.w);
                d[4] = pack2(b.x, b.x);
                d[5] = pack2(b.y, b.y);
                #pragma unroll
                for (int pr = 0; pr < 4; pr++) {
                    const u64* wr = sw + ((cc * 3 + kh) * 4 + pr) * 4;
                    ulonglong2 w01 = *(const ulonglong2*)wr;
                    u64 w2 = wr[2];
                    #pragma unroll
                    for (int px = 0; px < 4; px++) {
                        acc[pr][px] = fma2(w01.x, d[px],     acc[pr][px]);
                        acc[pr][px] = fma2(w01.y, d[px + 1], acc[pr][px]);
                        acc[pr][px] = fma2(w2,    d[px + 2], acc[pr][px]);
                    }
                }
            }
        }
        __syncthreads();
    }

    const size_t obase = (size_t)(bh + ty) * WW + bw + tx * 4;
    #pragma unroll
    for (int pr = 0; pr < 4; pr++) {
        float bva = bs[ocg0 + pr];
        float bvb = bs[ocg0 + pr + 4];
        float ra[4], rb[4];
        #pragma unroll
        for (int px = 0; px < 4; px++) {
            float2 f = unpack2(acc[pr][px]);
            float va = f.x + bva;
            float vb = f.y + bvb;
            if (RELU) {
                va = (va >= 0.f) ? va : 0.1f * va;
                vb = (vb >= 0.f) ? vb : 0.1f * vb;
            }
            ra[px] = va; rb[px] = vb;
        }
        *(float4*)&out[(size_t)(ocg0 + pr)     * HW + obase] =
            make_float4(ra[0], ra[1], ra[2], ra[3]);
        *(float4*)&out[(size_t)(ocg0 + pr + 4) * HW + obase] =
            make_float4(rb[0], rb[1], rb[2], rb[3]);
    }
}

#define CONV_SMEM (2*SIN_ELEMS*4 + 2*WCHUNK*8)

// ============================================================================
// Transpose: [C][HW] -> [HW][C].
// ============================================================================
__global__ void __launch_bounds__(256) transpose_kernel(
    const float* __restrict__ x, float* __restrict__ xT, int C)
{
    __shared__ float s[32][33];
    int p0 = blockIdx.x * 32;
    int c0 = blockIdx.y * 32;
    int tx = threadIdx.x & 31;
    int ty = threadIdx.x >> 5;
    #pragma unroll
    for (int i = 0; i < 32; i += 8)
        s[ty + i][tx] = x[(size_t)(c0 + ty + i) * HW + p0 + tx];
    __syncthreads();
    #pragma unroll
    for (int i = 0; i < 32; i += 8)
        xT[(size_t)(p0 + ty + i) * C + c0 + tx] = s[tx][ty + i];
}

// ============================================================================
// conv4 via mma.sync tf32 with 3-term error compensation (3xTF32).
// CTA: 128 px x 144 oc, 384 thr. K = 18 chunks (9 taps x 32 ci).
// B hi/lo prepacked; A hi/lo computed at fragment load.
// ============================================================================
#define C4_ASTR 36
#define C4_BSTR 152
#define C4_AELE (128 * C4_ASTR)
#define C4_BELE (32 * C4_BSTR)
#define C4_SMEM ((2 * C4_AELE + 4 * C4_BELE) * 4)

__global__ void __launch_bounds__(384) conv4_mma_kernel(
    const float* __restrict__ h1T,    // [HW][64]
    const float* __restrict__ w4Thi,  // [9][64][432]
    const float* __restrict__ w4Tlo,
    const float* __restrict__ b4,
    float* __restrict__ out4)         // [432][HW]
{
    extern __shared__ char dsm3[];
    float* sA   = (float*)dsm3;                                 // [2][128][36]
    float* sBhi = (float*)(dsm3 + 2 * C4_AELE * 4);             // [2][32][152]
    float* sBlo = (float*)(dsm3 + (2 * C4_AELE + 2 * C4_BELE) * 4);

    const int tid  = threadIdx.x;
    const int wid  = tid >> 5;
    const int lane = tid & 31;
    const int wm   = wid & 3;
    const int wn   = wid >> 2;
    const int ar   = lane >> 2;
    const int ac   = lane & 3;
    const int pbase = blockIdx.x * 128;
    const int nbase = blockIdx.y * 144;

    unsigned sa_addr  = (unsigned)__cvta_generic_to_shared(sA);
    unsigned sbh_addr = (unsigned)__cvta_generic_to_shared(sBhi);
    unsigned sbl_addr = (unsigned)__cvta_generic_to_shared(sBlo);

    auto load_chunk = [&](int chunk, int buf) {
        int tap = chunk >> 1;
        int ci0 = (chunk & 1) * 32;
        int dy = tap / 3 - 1, dx = tap % 3 - 1;
        unsigned ab = sa_addr + buf * (C4_AELE * 4);
        for (int li = tid; li < 1024; li += 384) {
            int px = li >> 3, j = li & 7;
            int p  = pbase + px;
            int iy = p / 192 + dy;
            int ix = p % 192 + dx;
            bool ok = (unsigned)iy < 192u && (unsigned)ix < 192u;
            const float* src = h1T + ((long)(iy * 192 + ix) << 6) + ci0 + j * 4;
            cp16z(ab + (px * C4_ASTR + j * 4) * 4, src, ok);
        }
        unsigned bh = sbh_addr + buf * (C4_BELE * 4);
        unsigned bl = sbl_addr + buf * (C4_BELE * 4);
        const size_t woff = ((size_t)tap * 64 + ci0) * 432 + nbase;
        for (int li = tid; li < 1152; li += 384) {
            int k = li / 36, j = li - k * 36;
            cp16(bh + (k * C4_BSTR + j * 4) * 4, w4Thi + woff + k * 432 + j * 4);
            cp16(bl + (k * C4_BSTR + j * 4) * 4, w4Tlo + woff + k * 432 + j * 4);
        }
    };

    float acc[2][6][4];
    #pragma unroll
    for (int m = 0; m < 2; m++)
        #pragma unroll
        for (int n = 0; n < 6; n++)
            #pragma unroll
            for (int q = 0; q < 4; q++) acc[m][n][q] = 0.f;

    load_chunk(0, 0);
    cp_commit();

    for (int c = 0; c < 18; c++) {
        if (c + 1 < 18) {
            load_chunk(c + 1, (c + 1) & 1);
            cp_commit();
            cp_wait<1>();
        } else {
            cp_wait<0>();
        }
        __syncthreads();

        const int buf = c & 1;
        const float* A   = sA   + buf * C4_AELE;
        const float* Bhi = sBhi + buf * C4_BELE;
        const float* Blo = sBlo + buf * C4_BELE;

        #pragma unroll
        for (int ks = 0; ks < 4; ks++) {
            const int k0 = ks * 8;
            unsigned ahi[2][4], alo[2][4];
            #pragma unroll
            for (int mt = 0; mt < 2; mt++) {
                const float* ap = A + (wm * 32 + mt * 16 + ar) * C4_ASTR + k0 + ac;
                float v0 = ap[0], v1 = ap[8 * C4_ASTR];
                float v2 = ap[4], v3 = ap[8 * C4_ASTR + 4];
                ahi[mt][0] = cvt_tf32(v0);
                ahi[mt][1] = cvt_tf32(v1);
                ahi[mt][2] = cvt_tf32(v2);
                ahi[mt][3] = cvt_tf32(v3);
                alo[mt][0] = cvt_tf32(v0 - __uint_as_float(ahi[mt][0]));
                alo[mt][1] = cvt_tf32(v1 - __uint_as_float(ahi[mt][1]));
                alo[mt][2] = cvt_tf32(v2 - __uint_as_float(ahi[mt][2]));
                alo[mt][3] = cvt_tf32(v3 - __uint_as_float(ahi[mt][3]));
            }
            unsigned bhi[6][2], blo[6][2];
            #pragma unroll
            for (int nt = 0; nt < 6; nt++) {
                const int bo = (k0 + ac) * C4_BSTR + wn * 48 + nt * 8 + ar;
                bhi[nt][0] = __float_as_uint(Bhi[bo]);
                bhi[nt][1] = __float_as_uint(Bhi[bo + 4 * C4_BSTR]);
                blo[nt][0] = __float_as_uint(Blo[bo]);
                blo[nt][1] = __float_as_uint(Blo[bo + 4 * C4_BSTR]);
            }
            #pragma unroll
            for (int mt = 0; mt < 2; mt++)
                #pragma unroll
                for (int nt = 0; nt < 6; nt++) {
                    mma_tf32(acc[mt][nt], ahi[mt], bhi[nt]);
                    mma_tf32(acc[mt][nt], alo[mt], bhi[nt]);
                    mma_tf32(acc[mt][nt], ahi[mt], blo[nt]);
                }
        }
        __syncthreads();
    }

    #pragma unroll
    for (int mt = 0; mt < 2; mt++) {
        #pragma unroll
        for (int nt = 0; nt < 6; nt++) {
            int rbase = pbase + wm * 32 + mt * 16 + ar;
            int cbase = nbase + wn * 48 + nt * 8 + 2 * ac;
            #pragma unroll
            for (int q = 0; q < 4; q++) {
                int row = rbase + (q >= 2 ? 8 : 0);
                int col = cbase + (q & 1);
                out4[(size_t)col * HW + row] = acc[mt][nt][q] + __ldg(b4 + col);
            }
        }
    }
}

// ============================================================================
// Fused deformable conv v4 (unchanged).
// ============================================================================
#define DPX 64
#define VAL_ELEMS (72 * DPX)
#define WG_ELEMS (72 * 64)
#define DEF_SMEM (2*VAL_ELEMS*4 + 2*WG_ELEMS*8)

__global__ void __launch_bounds__(256, 2) deform_kernel(
    const float* __restrict__ xT,
    const float* __restrict__ out4,
    const u64*   __restrict__ pwdT,
    const float* __restrict__ bs,
    float* __restrict__ out)
{
    extern __shared__ char dsm2[];
    float* val_s = (float*)dsm2;
    u64*   w_s   = (u64*)(dsm2 + 2 * VAL_ELEMS * 4);

    const int tid = threadIdx.x;
    const int pbase = blockIdx.x * DPX;
    const int o  = tid & 31;
    const int ps = tid >> 5;

    unsigned w_addr = (unsigned)__cvta_generic_to_shared(w_s);

    auto prefetch_w = [&](int g, int buf) {
        unsigned dbase = w_addr + buf * (WG_ELEMS * 8);
        const u64* src = pwdT + (size_t)g * WG_ELEMS;
        for (int li = tid; li < 2304; li += 256)
            cp16(dbase + li * 16, src + li * 2);
    };

    auto build_val = [&](int g, int buf) {
        float* vb = val_s + buf * VAL_ELEMS;
        for (int t = tid; t < 9 * DPX; t += 256) {
            int pix = t & (DPX - 1);
            int k   = t >> 6;
            int p   = pbase + pix;
            int ho  = p / WW;
            int wo  = p - ho * WW;

            float offy = 5.f * tanh_fast(out4[(g * 18 + k * 2)     * HW + p]);
            float offx = 5.f * tanh_fast(out4[(g * 18 + k * 2 + 1) * HW + p]);
            float mv   = sigmoid_fast(out4[(288 + g * 9 + k) * HW + p]);

            float py = (float)(ho - 1 + k / 3) + offy;
            float px = (float)(wo - 1 + k % 3) + offx;
            float y0 = floorf(py), x0 = floorf(px);
            float wy1 = py - y0, wx1 = px - x0;

            u64 v2[4] = {0ull, 0ull, 0ull, 0ull};

            auto corner = [&](float yf, float xf, float wc) {
                if (yf >= 0.f && yf <= (float)(HH - 1) &&
                    xf >= 0.f && xf <= (float)(WW - 1)) {
                    int iy = (int)yf, ix = (int)xf;
                    const ulonglong2* q =
                        (const ulonglong2*)(xT + ((size_t)(iy * WW + ix) << 7) + (g << 3));
                    ulonglong2 q0 = q[0], q1 = q[1];
                    u64 wc2 = pack2(wc, wc);
                    v2[0] = fma2(wc2, q0.x, v2[0]);
                    v2[1] = fma2(wc2, q0.y, v2[1]);
                    v2[2] = fma2(wc2, q1.x, v2[2]);
                    v2[3] = fma2(wc2, q1.y, v2[3]);
                }
            };
            corner(y0,       x0,       (1.f - wy1) * (1.f - wx1));
            corner(y0,       x0 + 1.f, (1.f - wy1) * wx1);
            corner(y0 + 1.f, x0,       wy1 * (1.f - wx1));
            corner(y0 + 1.f, x0 + 1.f, wy1 * wx1);

            u64 m2 = pack2(mv, mv);
            #pragma unroll
            for (int c2 = 0; c2 < 4; c2++) {
                float2 ff = unpack2(mul2(v2[c2], m2));
                vb[((c2 * 2)     * 9 + k) * DPX + pix] = ff.x;
                vb[((c2 * 2 + 1) * 9 + k) * DPX + pix] = ff.y;
            }
        }
    };

    u64 acc[2][4];
    #pragma unroll
    for (int a = 0; a < 2; a++)
        #pragma unroll
        for (int b = 0; b < 4; b++) acc[a][b] = 0ull;

    prefetch_w(0, 0);
    cp_commit();
    build_val(0, 0);

    for (int g = 0; g < 16; g++) {
        const int buf = g & 1;
        cp_wait<0>();
        __syncthreads();

        if (g < 15) {
            prefetch_w(g + 1, buf ^ 1);
            cp_commit();
        }

        const u64*   wb = w_s + buf * WG_ELEMS;
        const float* vv = val_s + buf * VAL_ELEMS + ps * 8;
        #pragma unroll 4
        for (int j = 0; j < 72; j++) {
            u64 w0 = wb[j * 64 + o];
            u64 w1 = wb[j * 64 + o + 32];
            const u64* vp = (const u64*)(vv + j * DPX);
            u64 v0 = vp[0], v1 = vp[1], v2 = vp[2], v3 = vp[3];
            acc[0][0] = fma2(w0, v0, acc[0][0]);
            acc[0][1] = fma2(w0, v1, acc[0][1]);
            acc[0][2] = fma2(w0, v2, acc[0][2]);
            acc[0][3] = fma2(w0, v3, acc[0][3]);
            acc[1][0] = fma2(w1, v0, acc[1][0]);
            acc[1][1] = fma2(w1, v1, acc[1][1]);
            acc[1][2] = fma2(w1, v2, acc[1][2]);
            acc[1][3] = fma2(w1, v3, acc[1][3]);
        }

        if (g < 15) build_val(g + 1, buf ^ 1);
    }

    float bv0 = bs[o], bv1 = bs[o + 32];
    float r0[8], r1[8];
    #pragma unroll
    for (int b = 0; b < 4; b++) {
        float2 fa = unpack2(acc[0][b]);
        float2 fb = unpack2(acc[1][b]);
        r0[b * 2] = fa.x + bv0; r0[b * 2 + 1] = fa.y + bv0;
        r1[b * 2] = fb.x + bv1; r1[b * 2 + 1] = fb.y + bv1;
    }
    float* o0 = &out[(size_t)o        * HW + pbase + ps * 8];
    float* o1 = &out[(size_t)(o + 32) * HW + pbase + ps * 8];
    *(float4*)(o0)     = make_float4(r0[0], r0[1], r0[2], r0[3]);
    *(float4*)(o0 + 4) = make_float4(r0[4], r0[5], r0[6], r0[7]);
    *(float4*)(o1)     = make_float4(r1[0], r1[1], r1[2], r1[3]);
    *(float4*)(o1 + 4) = make_float4(r1[4], r1[5], r1[6], r1[7]);
}

// ============================================================================
// launch
// ============================================================================
extern "C" void kernel_launch(void* const* d_in, const int* in_sizes, int n_in,
                              void* d_out, int out_size)
{
    const float* x      = (const float*)d_in[0];
    const float* cond   = (const float*)d_in[1];
    const float* weight = (const float*)d_in[2];
    const float* bias   = (const float*)d_in[3];
    const float* w1     = (const float*)d_in[4];
    const float* b1     = (const float*)d_in[5];
    const float* w2     = (const float*)d_in[6];
    const float* b2     = (const float*)d_in[7];
    const float* w3     = (const float*)d_in[8];
    const float* b3     = (const float*)d_in[9];
    const float* w4     = (const float*)d_in[10];
    const float* b4     = (const float*)d_in[11];
    float* out = (float*)d_out;

    float *h1, *h2, *h1T, *o4, *xT, *w4Thi, *w4Tlo;
    u64 *pw1, *pw2, *pw3, *pwdT;
    cudaGetSymbolAddress((void**)&h1,  g_h1);
    cudaGetSymbolAddress((void**)&h2,  g_h2);
    cudaGetSymbolAddress((void**)&h1T, g_h1T);
    cudaGetSymbolAddress((void**)&o4,  g_out4);
    cudaGetSymbolAddress((void**)&xT,  g_xT);
    cudaGetSymbolAddress((void**)&pw1, g_pw1);
    cudaGetSymbolAddress((void**)&pw2, g_pw2);
    cudaGetSymbolAddress((void**)&pw3, g_pw3);
    cudaGetSymbolAddress((void**)&pwdT, g_pwdT);
    cudaGetSymbolAddress((void**)&w4Thi, g_w4Thi);
    cudaGetSymbolAddress((void**)&w4Tlo, g_w4Tlo);

    prepack_all_kernel<<<(414720 + 255) / 256, 256>>>(
        w1, w2, w3, w4, weight, pw1, pw2, pw3, pwdT, w4Thi, w4Tlo);

    cudaFuncSetAttribute(conv3x3_kernel<192, true>,
                         cudaFuncAttributeMaxDynamicSharedMemorySize, CONV_SMEM);
    cudaFuncSetAttribute(conv3x3_kernel<64, true>,
                         cudaFuncAttributeMaxDynamicSharedMemorySize, CONV_SMEM);
    cudaFuncSetAttribute(conv4_mma_kernel,
                         cudaFuncAttributeMaxDynamicSharedMemorySize, C4_SMEM);
    cudaFuncSetAttribute(deform_kernel,
                         cudaFuncAttributeMaxDynamicSharedMemorySize, DEF_SMEM);

    dim3 cgrid(3, 12, 8);
    conv3x3_kernel<192, true><<<cgrid, 256, CONV_SMEM>>>(cond, pw1, b1, h1);
    conv3x3_kernel< 64, true><<<cgrid, 256, CONV_SMEM>>>(h1,   pw2, b2, h2);
    conv3x3_kernel< 64, true><<<cgrid, 256, CONV_SMEM>>>(h2,   pw3, b3, h1);

    transpose_kernel<<<dim3(1152, 2), 256>>>(h1, h1T, 64);
    conv4_mma_kernel<<<dim3(288, 3), 384, C4_SMEM>>>(h1T, w4Thi, w4Tlo, b4, o4);

    transpose_kernel<<<dim3(1152, 4), 256>>>(x, xT, 128);
    deform_kernel<<<HW / DPX, 256, DEF_SMEM>>>(xT, o4, pwdT, bias, out);
}